// round 13
// baseline (speedup 1.0000x reference)
#include <cuda_runtime.h>
#include <cuda_fp16.h>
#include <math.h>

// Problem constants
#define BS   128
#define NE   32
#define NA   8
#define TE   8
#define TA   4
#define WD   300
#define HD   1024
#define G3   900          // 3*WD
#define NG   (BS*NE)      // 4096
#define NATT (NG*NA)      // 32768
#define NNODE 9
#define V    30522
#define KP3  304          // WD padded to multiple of 8

typedef unsigned long long u64;
typedef unsigned int u32;

// ---------------- scratch ----------------------------------------------------
__device__ __half g_xp_ent [NG   * TE * G3];
__device__ __half g_xp_attr[NATT * TA * G3];
__device__ __half g_gh_ent [NG   * G3];
__device__ __half g_gh_attr[NATT * G3];
__device__ float g_h_ent  [NG   * WD];
__device__ float g_h_attr [NATT * WD];
__device__ float g_nodes  [NG * NNODE * HD];
__device__ float g_va     [HD];
__device__ float g_vb     [HD];
// fp16 operand buffers (hi only — single-pass GEMM)
__device__ __half g_emb_hi[V * KP3];
__device__ __half g_wihe_hi[G3 * KP3];
__device__ __half g_whhe_hi[G3 * KP3];
__device__ __half g_wiha_hi[G3 * KP3];
__device__ __half g_whha_hi[G3 * KP3];
__device__ __half g_wfc_hi[HD * KP3];
__device__ __half g_wg_hi[HD * HD];
__device__ __half g_he_hi[NG * KP3];
__device__ __half g_ha_hi[NATT * KP3];
__device__ __half g_mix_hi[NG * HD];
// counters: [0..TE] cntE, [10..10+TA] cntA, [20] pcE, [21] pcA
__device__ int g_ctr[32];
__device__ int g_off_ent [TE + 1];
__device__ int g_perm_ent[NG];
__device__ int g_mcnt_ent[TE];
__device__ int g_off_attr [TA + 1];
__device__ int g_perm_attr[NATT];
__device__ int g_mcnt_attr[TA];
__device__ int g_gtok_ent[NG * TE];
__device__ int g_orow_ent[NG * TE];
__device__ int g_gtok_attr[NATT * TA];
__device__ int g_orow_attr[NATT * TA];

// ---------------- helpers ------------------------------------------------------
__device__ __forceinline__ u32 smem_u32(const void* p) {
    u32 a;
    asm("{ .reg .u64 t; cvta.to.shared.u64 t, %1; cvt.u32.u64 %0, t; }"
        : "=r"(a) : "l"(p));
    return a;
}

#define LDSM_X4(r, addr) \
    asm volatile("ldmatrix.sync.aligned.m8n8.x4.shared.b16 {%0,%1,%2,%3}, [%4];" \
        : "=r"((r)[0]), "=r"((r)[1]), "=r"((r)[2]), "=r"((r)[3]) : "r"(addr))

#define LDSM_X2(r0, r1, addr) \
    asm volatile("ldmatrix.sync.aligned.m8n8.x2.shared.b16 {%0,%1}, [%2];" \
        : "=r"(r0), "=r"(r1) : "r"(addr))

#define MMA16816(c, a, b0, b1) \
    asm volatile("mma.sync.aligned.m16n8k16.row.col.f32.f16.f16.f32 " \
        "{%0,%1,%2,%3}, {%4,%5,%6,%7}, {%8,%9}, {%0,%1,%2,%3};" \
        : "+f"((c)[0]), "+f"((c)[1]), "+f"((c)[2]), "+f"((c)[3]) \
        : "r"((a)[0]), "r"((a)[1]), "r"((a)[2]), "r"((a)[3]), "r"(b0), "r"(b1))

#define CP16(dst, src, sz) \
    asm volatile("cp.async.cg.shared.global [%0], [%1], 16, %2;" \
        :: "r"(dst), "l"(src), "r"(sz) : "memory")
#define CPCOMMIT() asm volatile("cp.async.commit_group;" ::: "memory")
#define CPWAIT1()  asm volatile("cp.async.wait_group 1;"  ::: "memory")
#define CPWAIT0()  asm volatile("cp.async.wait_group 0;"  ::: "memory")

#define SWZ(o) ((o) ^ (((o) >> 3) & 0x70u))

__device__ __forceinline__ u64 cvt4h(float4 v) {
    unsigned short h[4];
    const float* pv = &v.x;
#pragma unroll
    for (int i = 0; i < 4; ++i) h[i] = __half_as_ushort(__float2half(pv[i]));
    return (u64)h[0] | ((u64)h[1] << 16) | ((u64)h[2] << 32) | ((u64)h[3] << 48);
}
__device__ __forceinline__ float4 ld4h(const __half* p) {
    __half2 a = *(const __half2*)p;
    __half2 b = *(const __half2*)(p + 2);
    float2 fa = __half22float2(a), fb = __half22float2(b);
    return make_float4(fa.x, fa.y, fb.x, fb.y);
}

// ---------------- fp32 -> fp16 conversion -------------------------------------
__global__ void cvt_rows_hi(const float* __restrict__ x,
                            __half* __restrict__ hi,
                            int rows, int K, int KP)
{
    int q = KP / 4;
    int idx = blockIdx.x * blockDim.x + threadIdx.x;
    int r = idx / q;
    if (r >= rows) return;
    int i4 = (idx - r * q) * 4;
    float4 v = make_float4(0.f, 0.f, 0.f, 0.f);
    if (i4 + 4 <= K) v = *(const float4*)(x + (long)r * K + i4);
    *(u64*)(hi + (long)r * KP + i4) = cvt4h(v);
}

__global__ void cvt_w4(const float* s0, const float* s1, const float* s2, const float* s3,
                       __half* h0, __half* h1, __half* h2, __half* h3)
{
    const float* src; __half* hi;
    switch (blockIdx.y) {
        case 0: src = s0; hi = h0; break;
        case 1: src = s1; hi = h1; break;
        case 2: src = s2; hi = h2; break;
        default: src = s3; hi = h3; break;
    }
    int q = KP3 / 4;
    int idx = blockIdx.x * blockDim.x + threadIdx.x;
    int r = idx / q;
    if (r >= G3) return;
    int i4 = (idx - r * q) * 4;
    float4 v = make_float4(0.f, 0.f, 0.f, 0.f);
    if (i4 + 4 <= WD) v = *(const float4*)(src + (long)r * WD + i4);
    *(u64*)(hi + (long)r * KP3 + i4) = cvt4h(v);
}

// ---------------- tensor GEMM (fp16 single-pass, cp.async pipeline) ----------
#define TM 128
#define TN 128
#define CK 64
#define OFF_AHI 0u
#define OFF_BHI 16384u
#define STAGE   32768u
#define TG_SMEM 65536u

__global__ void __launch_bounds__(256, 2)
tgemm(const __half* __restrict__ Ahi,
      const int* __restrict__ gather,
      const __half* __restrict__ Bhi,
      const float* __restrict__ bias,
      void* __restrict__ C, int M, int N, int K, int KP, int act, int outMap,
      const int* __restrict__ mlimit, const int* __restrict__ mlo,
      const int* __restrict__ orow, int outHalf)
{
    extern __shared__ char smem[];
    int hiM = M;
    if (mlimit) { int v = *mlimit; if (v < hiM) hiM = v; }
    int loM = mlo ? *mlo : 0;
    const int m0 = blockIdx.x * TM;
    const int n0 = blockIdx.y * TN;
    if (m0 >= hiM || m0 + TM <= loM) return;

    const u32 sbase = smem_u32(smem);
    const int tid  = threadIdx.x;
    const int wid  = tid >> 5;
    const int lane = tid & 31;
    const int wm   = wid >> 1;
    const int wn   = wid & 1;

    const int k8   = (tid & 7) * 8;
    const int rloc = tid >> 3;
    long roA[4], roB[4];
    bool vA[4], vB[4];
    u32  swR[4];
#pragma unroll
    for (int it = 0; it < 4; ++it) {
        int r = rloc + 32 * it;
        int m = m0 + r;
        vA[it] = (m >= loM && m < hiM);
        int src = vA[it] ? (gather ? gather[m] : m) : 0;
        roA[it] = (long)src * KP;
        int n = n0 + r;
        vB[it] = (n < N);
        roB[it] = (long)(vB[it] ? n : 0) * KP;
        swR[it] = SWZ((u32)(r * 128 + k8 * 2));
    }

#define FILL_CHUNK(cc, st) do { \
    int gk_ = (cc) * CK + k8; \
    u32 sb_ = sbase + (u32)(st) * STAGE; \
    bool kok_ = (gk_ < KP); \
    _Pragma("unroll") \
    for (int it = 0; it < 4; ++it) { \
        bool aok = vA[it] && kok_; u32 asz = aok ? 16u : 0u; \
        const __half* pa1 = aok ? (Ahi + roA[it] + gk_) : Ahi; \
        CP16(sb_ + OFF_AHI + swR[it], pa1, asz); \
        bool bok = vB[it] && kok_; u32 bsz = bok ? 16u : 0u; \
        const __half* pb1 = bok ? (Bhi + roB[it] + gk_) : Bhi; \
        CP16(sb_ + OFF_BHI + swR[it], pb1, bsz); \
    } \
    CPCOMMIT(); \
} while (0)

    const u32 rbA0 = (u32)((wm * 32 + (lane & 15)) * 128);
    const u32 rbA1 = rbA0 + 16u * 128u;
    const u32 rbB  = (u32)((wn * 64 + (lane & 7)) * 128);
    const u32 xorq = (u32)(lane & 7);
    const u32 qAh  = (u32)(lane >> 4);
    const u32 qBh  = (u32)((lane >> 3) & 1);

    // number of valid 8-col MMA blocks for this warp (skip all-zero N blocks)
    int nvLoc = N - n0 - wn * 64;
    int nbMax = nvLoc >= 64 ? 8 : (nvLoc <= 0 ? 0 : (nvLoc + 7) >> 3);

    float acc[2][8][4];
#pragma unroll
    for (int i = 0; i < 2; ++i)
#pragma unroll
        for (int j = 0; j < 8; ++j)
#pragma unroll
            for (int q = 0; q < 4; ++q) acc[i][j][q] = 0.f;

    const int nc = (K + CK - 1) / CK;

    FILL_CHUNK(0, 0);
    for (int c = 0; c < nc; ++c) {
        if (c + 1 < nc) { FILL_CHUNK(c + 1, (c + 1) & 1); CPWAIT1(); }
        else            { CPWAIT0(); }
        __syncthreads();

        const u32 stb = sbase + (u32)(c & 1) * STAGE;
        const u32 ab = stb + OFF_AHI;
        const u32 bb = stb + OFF_BHI;
#pragma unroll
        for (int ks = 0; ks < 4; ++ks) {
            if (c * CK + ks * 16 >= KP) break;     // K pad guard (zeros only)
            u32 qa = (((u32)(2 * ks) + qAh) ^ xorq) * 16u;
            u32 a0[4], a1[4];
            LDSM_X4(a0, ab + rbA0 + qa);
            LDSM_X4(a1, ab + rbA1 + qa);
            u32 qb = (((u32)(2 * ks) + qBh) ^ xorq) * 16u;
#pragma unroll
            for (int nb = 0; nb < 8; ++nb) {
                if (nb >= nbMax) break;            // N pad guard (unstored cols)
                u32 b0, b1;
                LDSM_X2(b0, b1, bb + rbB + (u32)nb * 1024u + qb);
                MMA16816(acc[0][nb], a0, b0, b1);
                MMA16816(acc[1][nb], a1, b0, b1);
            }
        }
        __syncthreads();
    }
#undef FILL_CHUNK

#pragma unroll
    for (int mi = 0; mi < 2; ++mi) {
#pragma unroll
        for (int half = 0; half < 2; ++half) {
            int m = m0 + wm * 32 + mi * 16 + (lane >> 2) + half * 8;
            if (m < loM || m >= hiM) continue;
            int mm = orow ? orow[m] : m;
            long base;
            if (outMap == 0)      base = (long)mm * N;
            else if (outMap == 1) base = (long)mm * NNODE * HD;
            else                  base = ((long)(mm >> 3) * NNODE + 1 + (mm & 7)) * (long)HD;
#pragma unroll
            for (int nb = 0; nb < 8; ++nb) {
                int n = n0 + wn * 64 + nb * 8 + (lane & 3) * 2;
                if (n >= N) continue;
                float x0 = acc[mi][nb][half * 2 + 0];
                float x1 = acc[mi][nb][half * 2 + 1];
                if (bias) { x0 += bias[n]; x1 += bias[n + 1]; }
                if (act == 1)      { x0 = fmaxf(x0, 0.f); x1 = fmaxf(x1, 0.f); }
                else if (act == 2) { x0 = x0 > 0.f ? x0 : expm1f(x0);
                                     x1 = x1 > 0.f ? x1 : expm1f(x1); }
                if (outHalf) {
                    *(__half2*)((__half*)C + base + n) = __floats2half2_rn(x0, x1);
                } else {
                    *(float2*)((float*)C + base + n) = make_float2(x0, x1);
                }
            }
        }
    }
}

// ---------------- fused preprocessing (ent + attr) ---------------------------
__device__ __forceinline__ int clampL(int L, int T) {
    return L < 1 ? 1 : (L > T ? T : L);
}
__global__ void hist2(const int* __restrict__ lenE, const int* __restrict__ lenA,
                      int* __restrict__ cntE, int* __restrict__ cntA)
{
    int i = blockIdx.x * blockDim.x + threadIdx.x;
    if (i < NG)   atomicAdd(&cntE[clampL(lenE[i], TE)], 1);
    if (i < NATT) atomicAdd(&cntA[clampL(lenA[i], TA)], 1);
}
__global__ void offsets2(const int* __restrict__ cntE, int* __restrict__ offE,
                         int* __restrict__ mcntE,
                         const int* __restrict__ cntA, int* __restrict__ offA,
                         int* __restrict__ mcntA)
{
    if (threadIdx.x == 0) {
        int run = 0;
        for (int L = TE; L >= 1; --L) { offE[L] = run; run += cntE[L]; }
        for (int t = 0; t < TE; ++t) {
            int s = 0;
            for (int L = t + 1; L <= TE; ++L) s += cntE[L];
            mcntE[t] = s;
        }
    } else if (threadIdx.x == 1) {
        int run = 0;
        for (int L = TA; L >= 1; --L) { offA[L] = run; run += cntA[L]; }
        for (int t = 0; t < TA; ++t) {
            int s = 0;
            for (int L = t + 1; L <= TA; ++L) s += cntA[L];
            mcntA[t] = s;
        }
    }
}
__global__ void scatter2(const int* __restrict__ lenE, const int* __restrict__ lenA,
                         int* __restrict__ offE, int* __restrict__ permE,
                         int* __restrict__ offA, int* __restrict__ permA)
{
    int i = blockIdx.x * blockDim.x + threadIdx.x;
    if (i < NG) {
        int pos = atomicAdd(&offE[clampL(lenE[i], TE)], 1);
        permE[pos] = i;
    }
    if (i < NATT) {
        int pos = atomicAdd(&offA[clampL(lenA[i], TA)], 1);
        permA[pos] = i;
    }
}
__global__ void pairs2(const int* __restrict__ tokE, const int* __restrict__ lenE,
                       int* __restrict__ pcE, int* __restrict__ gtokE, int* __restrict__ orowE,
                       const int* __restrict__ tokA, const int* __restrict__ lenA,
                       int* __restrict__ pcA, int* __restrict__ gtokA, int* __restrict__ orowA)
{
    int p = blockIdx.x * blockDim.x + threadIdx.x;
    if (p < NG * TE) {
        int i = p / TE, t = p - i * TE;
        if (t < clampL(lenE[i], TE)) {
            int pos = atomicAdd(pcE, 1);
            gtokE[pos] = tokE[p];
            orowE[pos] = p;
        }
    }
    if (p < NATT * TA) {
        int i = p / TA, t = p - i * TA;
        if (t < clampL(lenA[i], TA)) {
            int pos = atomicAdd(pcA, 1);
            gtokA[pos] = tokA[p];
            orowA[pos] = p;
        }
    }
}

// ---------------- GRU gate update (fp16 xp/gh; t0 path uses gh = bhh) --------
__global__ void gru_gate4(const __half* __restrict__ xp,
                          const __half* __restrict__ gh,
                          const float* __restrict__ bhh_t0,   // non-null => t==0
                          float* __restrict__ h,
                          __half* __restrict__ hhi,
                          const int* __restrict__ perm,
                          const int* __restrict__ mcnt,
                          int t, int T)
{
    const int Q = WD / 4;   // 75
    int idx = blockIdx.x * blockDim.x + threadIdx.x;
    int i = idx / Q;
    if (i >= *mcnt) return;
    int d = idx - i * Q;
    int orig = perm[i];
    const __half* x = xp + ((long)orig * T + t) * G3;
    float4* hp = (float4*)(h + (long)orig * WD);

    float4 xr = ld4h(x + 4 * d);
    float4 xz = ld4h(x + WD + 4 * d);
    float4 xn = ld4h(x + 2 * WD + 4 * d);
    float4 gr, gz, gn, hv;
    if (bhh_t0) {
        const float4* b = (const float4*)bhh_t0;
        gr = b[d]; gz = b[Q + d]; gn = b[2 * Q + d];
        hv = make_float4(0.f, 0.f, 0.f, 0.f);
    } else {
        const __half* g = gh + (long)i * G3;
        gr = ld4h(g + 4 * d);
        gz = ld4h(g + WD + 4 * d);
        gn = ld4h(g + 2 * WD + 4 * d);
        hv = hp[d];
    }

    float4 res;
    const float* pxr = &xr.x; const float* pxz = &xz.x; const float* pxn = &xn.x;
    const float* pgr = &gr.x; const float* pgz = &gz.x; const float* pgn = &gn.x;
    const float* phv = &hv.x; float* pres = &res.x;
#pragma unroll
    for (int c = 0; c < 4; ++c) {
        float r = 1.f / (1.f + expf(-(pxr[c] + pgr[c])));
        float z = 1.f / (1.f + expf(-(pxz[c] + pgz[c])));
        float n = tanhf(pxn[c] + r * pgn[c]);
        pres[c] = (1.f - z) * n + z * phv[c];
    }
    hp[d] = res;
    *(u64*)(hhi + (long)orig * KP3 + 4 * d) = cvt4h(res);
}

// ---------------- va/vb = Wg^T a_src / Wg^T a_dst ----------------------------
__global__ void wgt_vec_kernel(const float* __restrict__ Wg,
                               const float* __restrict__ a_src,
                               const float* __restrict__ a_dst,
                               float* __restrict__ va, float* __restrict__ vb)
{
    int k = blockIdx.x * blockDim.x + threadIdx.x;
    if (k >= HD) return;
    float sa = 0.f, sb = 0.f;
    for (int d = 0; d < HD; ++d) {
        float w = Wg[(long)d * HD + k];
        sa += w * a_src[d];
        sb += w * a_dst[d];
    }
    va[k] = sa;
    vb[k] = sb;
}

// ---------------- GAT dots + softmax + node mix (writes fp16 hi) -------------
__global__ void gat_mix_kernel(const float* __restrict__ nodes,
                               const float* __restrict__ va,
                               const float* __restrict__ vb,
                               const unsigned char* __restrict__ amask,
                               __half* __restrict__ mhi)
{
    int g = blockIdx.x;
    const float* base = nodes + (long)g * NNODE * HD;
    __shared__ float sdots[10];
    __shared__ float salpha[NNODE];

    int tid  = threadIdx.x;
    int warp = tid >> 5, lane = tid & 31;

    float partial = 0.f;
    if (warp < 9) {
        const float* row = base + warp * HD;
        for (int d = lane; d < HD; d += 32) partial += row[d] * vb[d];
    } else {
        for (int d = lane; d < HD; d += 32) partial += base[d] * va[d];
    }
#pragma unroll
    for (int off = 16; off; off >>= 1)
        partial += __shfl_down_sync(0xffffffffu, partial, off);
    if (lane == 0) sdots[warp] = partial;
    __syncthreads();

    if (tid == 0) {
        float es0 = sdots[9];
        float e[NNODE];
#pragma unroll
        for (int j = 0; j < NNODE; ++j) {
            bool valid;
            if (j == 0) valid = true;
            else {
                const unsigned char* mk = amask + ((long)g * NA + (j - 1)) * TA;
                valid = !(mk[0] && mk[1] && mk[2] && mk[3]);
            }
            if (valid) {
                float v = es0 + sdots[j];
                e[j] = v > 0.f ? v : 0.2f * v;
            } else e[j] = -1e9f;
        }
        float mx = e[0];
#pragma unroll
        for (int j = 1; j < NNODE; ++j) mx = fmaxf(mx, e[j]);
        float s = 0.f, ex[NNODE];
#pragma unroll
        for (int j = 0; j < NNODE; ++j) { ex[j] = expf(e[j] - mx); s += ex[j]; }
        float inv = 1.f / s;
#pragma unroll
        for (int j = 0; j < NNODE; ++j) salpha[j] = ex[j] * inv;
    }
    __syncthreads();

    for (int d4 = tid; d4 < HD / 4; d4 += blockDim.x) {
        float4 s4;
        float* ps = &s4.x;
#pragma unroll
        for (int q = 0; q < 4; ++q) {
            int d = d4 * 4 + q;
            float s = 0.f;
#pragma unroll
            for (int j = 0; j < NNODE; ++j) s += salpha[j] * base[j * HD + d];
            ps[q] = s;
        }
        *(u64*)(mhi + (long)g * HD + 4 * d4) = cvt4h(s4);
    }
}

// ---------------- launch ------------------------------------------------------
extern "C" void kernel_launch(void* const* d_in, const int* in_sizes, int n_in,
                              void* d_out, int out_size)
{
    const int*   ent_tok  = (const int*)  d_in[0];
    const int*   ent_len  = (const int*)  d_in[1];
    const int*   at_tok   = (const int*)  d_in[3];
    const int*   at_len   = (const int*)  d_in[4];
    const unsigned char* at_mask = (const unsigned char*)d_in[5];
    const float* emb      = (const float*)d_in[6];
    const float* Wih_ent  = (const float*)d_in[7];
    const float* Whh_ent  = (const float*)d_in[8];
    const float* bih_ent  = (const float*)d_in[9];
    const float* bhh_ent  = (const float*)d_in[10];
    const float* Wih_attr = (const float*)d_in[11];
    const float* Whh_attr = (const float*)d_in[12];
    const float* bih_attr = (const float*)d_in[13];
    const float* bhh_attr = (const float*)d_in[14];
    const float* Wfc      = (const float*)d_in[15];
    const float* bfc      = (const float*)d_in[16];
    const float* Wg       = (const float*)d_in[17];
    const float* a_src    = (const float*)d_in[18];
    const float* a_dst    = (const float*)d_in[19];
    float* out = (float*)d_out;

    static cudaStream_t s2 = nullptr, s3 = nullptr;
    static cudaEvent_t evF = nullptr, evJ = nullptr, evFC = nullptr;
    static cudaEvent_t evG[TA] = {};
    if (!s2) {
        cudaStreamCreateWithFlags(&s2, cudaStreamNonBlocking);
        cudaStreamCreateWithFlags(&s3, cudaStreamNonBlocking);
        cudaEventCreateWithFlags(&evF, cudaEventDisableTiming);
        cudaEventCreateWithFlags(&evJ, cudaEventDisableTiming);
        cudaEventCreateWithFlags(&evFC, cudaEventDisableTiming);
        for (int t = 0; t < TA; ++t)
            cudaEventCreateWithFlags(&evG[t], cudaEventDisableTiming);
    }

    __half *xp_ent, *xp_attr, *ghE, *ghA;
    float *h_ent, *h_attr, *nodes, *va, *vb;
    int *ctr, *offE, *permE, *mcntE, *offA, *permA, *mcntA;
    int *gtokE, *orowE, *gtokA, *orowA;
    __half *embH, *wiheH, *whheH, *wihaH, *whhaH, *wfcH, *wgH;
    __half *heH, *haH, *mixH;

    cudaGetSymbolAddress((void**)&xp_ent,  g_xp_ent);
    cudaGetSymbolAddress((void**)&xp_attr, g_xp_attr);
    cudaGetSymbolAddress((void**)&ghE,     g_gh_ent);
    cudaGetSymbolAddress((void**)&ghA,     g_gh_attr);
    cudaGetSymbolAddress((void**)&h_ent,   g_h_ent);
    cudaGetSymbolAddress((void**)&h_attr,  g_h_attr);
    cudaGetSymbolAddress((void**)&nodes,   g_nodes);
    cudaGetSymbolAddress((void**)&va,      g_va);
    cudaGetSymbolAddress((void**)&vb,      g_vb);
    cudaGetSymbolAddress((void**)&ctr,   g_ctr);
    cudaGetSymbolAddress((void**)&offE,  g_off_ent);
    cudaGetSymbolAddress((void**)&permE, g_perm_ent);
    cudaGetSymbolAddress((void**)&mcntE, g_mcnt_ent);
    cudaGetSymbolAddress((void**)&offA,  g_off_attr);
    cudaGetSymbolAddress((void**)&permA, g_perm_attr);
    cudaGetSymbolAddress((void**)&mcntA, g_mcnt_attr);
    cudaGetSymbolAddress((void**)&gtokE, g_gtok_ent);
    cudaGetSymbolAddress((void**)&orowE, g_orow_ent);
    cudaGetSymbolAddress((void**)&gtokA, g_gtok_attr);
    cudaGetSymbolAddress((void**)&orowA, g_orow_attr);
    cudaGetSymbolAddress((void**)&embH,  g_emb_hi);
    cudaGetSymbolAddress((void**)&wiheH, g_wihe_hi);
    cudaGetSymbolAddress((void**)&whheH, g_whhe_hi);
    cudaGetSymbolAddress((void**)&wihaH, g_wiha_hi);
    cudaGetSymbolAddress((void**)&whhaH, g_whha_hi);
    cudaGetSymbolAddress((void**)&wfcH,  g_wfc_hi);
    cudaGetSymbolAddress((void**)&wgH,   g_wg_hi);
    cudaGetSymbolAddress((void**)&heH,   g_he_hi);
    cudaGetSymbolAddress((void**)&haH,   g_ha_hi);
    cudaGetSymbolAddress((void**)&mixH,  g_mix_hi);

    int* cntE = ctr + 0;
    int* cntA = ctr + 10;
    int* pcE  = ctr + 20;
    int* pcA  = ctr + 21;

    cudaFuncSetAttribute(tgemm, cudaFuncAttributeMaxDynamicSharedMemorySize, TG_SMEM);

    cudaMemsetAsync(ctr, 0, 32 * sizeof(int));

    // Wg conversion + attention vectors on s2 (independent of main prefix)
    cvt_rows_hi<<<(HD * (HD / 4) + 255) / 256, 256, 0, s2>>>(Wg, wgH, HD, HD, HD);
    wgt_vec_kernel<<<(HD + 255) / 256, 256, 0, s2>>>(Wg, a_src, a_dst, va, vb);

    // main-prefix conversions + preprocessing
    const int q3 = KP3 / 4;
    cvt_rows_hi<<<(V * q3 + 255) / 256, 256>>>(emb, embH, V, WD, KP3);
    cvt_w4<<<dim3((G3 * q3 + 255) / 256, 4), 256>>>(
        Wih_ent, Whh_ent, Wih_attr, Whh_attr, wiheH, whheH, wihaH, whhaH);
    cvt_rows_hi<<<(HD * q3 + 255) / 256, 256>>>(Wfc, wfcH, HD, WD, KP3);

    hist2<<<(NATT + 255) / 256, 256>>>(ent_len, at_len, cntE, cntA);
    offsets2<<<1, 32>>>(cntE, offE, mcntE, cntA, offA, mcntA);
    scatter2<<<(NATT + 255) / 256, 256>>>(ent_len, at_len, offE, permE, offA, permA);
    pairs2<<<(NATT * TA + 255) / 256, 256>>>(ent_tok, ent_len, pcE, gtokE, orowE,
                                             at_tok, at_len, pcA, gtokA, orowA);

    // fork entity chain (incl. its xp GEMM) right after preprocessing
    cudaEventRecord(evF, 0);
    cudaStreamWaitEvent(s2, evF, 0);

    const int nt900  = (G3 + TN - 1) / TN;   // 8
    const int nt1024 = HD / TN;              // 8

    // ---- entity chain (stream s2): xp_ent + GRU + FC ----
    tgemm<<<dim3(NG * TE / TM, nt900), 256, TG_SMEM, s2>>>(
        embH, gtokE, wiheH, bih_ent, xp_ent,
        NG * TE, G3, WD, KP3, 0, 0, pcE, nullptr, orowE, 1);
    gru_gate4<<<(NG * 75 + 255) / 256, 256, 0, s2>>>(
        xp_ent, nullptr, bhh_ent, h_ent, heH, permE, mcntE + 0, 0, TE);
    for (int t = 1; t < TE; ++t) {
        tgemm<<<dim3(NG / TM, nt900), 256, TG_SMEM, s2>>>(
            heH, permE, whheH, bhh_ent, ghE,
            NG, G3, WD, KP3, 0, 0, mcntE + t, nullptr, nullptr, 1);
        gru_gate4<<<(NG * 75 + 255) / 256, 256, 0, s2>>>(
            xp_ent, ghE, nullptr, h_ent, heH, permE, mcntE + t, t, TE);
    }
    tgemm<<<dim3(NG / TM, nt1024), 256, TG_SMEM, s2>>>(
        heH, nullptr, wfcH, bfc, nodes,
        NG, HD, WD, KP3, 1, 1, nullptr, nullptr, nullptr, 0);
    cudaEventRecord(evJ, s2);

    // ---- attribute chain (main stream) with retired-row FC slices on s3 ----
    tgemm<<<dim3(NATT * TA / TM, nt900), 256, TG_SMEM>>>(
        embH, gtokA, wihaH, bih_attr, xp_attr,
        NATT * TA, G3, WD, KP3, 0, 0, pcA, nullptr, orowA, 1);
    gru_gate4<<<(NATT * 75 + 255) / 256, 256>>>(
        xp_attr, nullptr, bhh_attr, h_attr, haH, permA, mcntA + 0, 0, TA);
    cudaEventRecord(evG[0], 0);
    for (int t = 1; t < TA; ++t) {
        tgemm<<<dim3(NATT / TM, nt900), 256, TG_SMEM>>>(
            haH, permA, whhaH, bhh_attr, ghA,
            NATT, G3, WD, KP3, 0, 0, mcntA + t, nullptr, nullptr, 1);
        gru_gate4<<<(NATT * 75 + 255) / 256, 256>>>(
            xp_attr, ghA, nullptr, h_attr, haH, permA, mcntA + t, t, TA);
        cudaEventRecord(evG[t], 0);
    }
    // FC slices: after gate t, rows [mcnt[t+1], mcnt[t]) are final
    for (int t = 0; t < TA; ++t) {
        cudaStreamWaitEvent(s3, evG[t], 0);
        const int* hiP = mcntA + t;
        const int* loP = (t + 1 < TA) ? (mcntA + t + 1) : nullptr;  // lo = 0 at last
        tgemm<<<dim3(NATT / TM, nt1024), 256, TG_SMEM, s3>>>(
            haH, permA, wfcH, bfc, nodes,
            NATT, HD, WD, KP3, 1, 2, hiP, loP, permA, 0);
    }
    cudaEventRecord(evFC, s3);

    // join entity + FC streams
    cudaStreamWaitEvent(0, evJ, 0);
    cudaStreamWaitEvent(0, evFC, 0);

    // GAT: dots + alpha + mix (fp16 out)
    gat_mix_kernel<<<NG, 320>>>(nodes, va, vb, at_mask, mixH);

    // out = elu(mix @ Wg^T)
    tgemm<<<dim3(NG / TM, nt1024), 256, TG_SMEM>>>(
        mixH, nullptr, wgH, nullptr, out,
        NG, HD, HD, HD, 2, 0, nullptr, nullptr, nullptr, 0);
}

// round 15
// speedup vs baseline: 1.1455x; 1.1455x over previous
#include <cuda_runtime.h>
#include <cuda_fp16.h>
#include <math.h>

// Problem constants
#define BS   128
#define NE   32
#define NA   8
#define TE   8
#define TA   4
#define WD   300
#define HD   1024
#define G3   900          // 3*WD
#define NG   (BS*NE)      // 4096
#define NATT (NG*NA)      // 32768
#define NNODE 9
#define V    30522
#define KP3  304          // WD padded to multiple of 8

typedef unsigned long long u64;
typedef unsigned int u32;

// ---------------- scratch ----------------------------------------------------
__device__ __half g_xp_ent [NG   * TE * G3];
__device__ __half g_xp_attr[NATT * TA * G3];
__device__ __half g_gh_ent [NG   * G3];
__device__ __half g_gh_attr[NATT * G3];
__device__ float g_h_ent  [NG   * WD];
__device__ float g_h_attr [NATT * WD];
__device__ float g_nodes  [NG * NNODE * HD];
__device__ float g_va     [HD];
__device__ float g_vb     [HD];
// fp16 operand buffers (hi only — single-pass GEMM)
__device__ __half g_emb_hi[V * KP3];
__device__ __half g_wihe_hi[G3 * KP3];
__device__ __half g_whhe_hi[G3 * KP3];
__device__ __half g_wiha_hi[G3 * KP3];
__device__ __half g_whha_hi[G3 * KP3];
__device__ __half g_wfc_hi[HD * KP3];
__device__ __half g_wg_hi[HD * HD];
__device__ __half g_he_hi[NG * KP3];
__device__ __half g_ha_hi[NATT * KP3];
__device__ __half g_mix_hi[NG * HD];
// counters
__device__ int g_ctr[32];
__device__ int g_off_ent [TE + 1];
__device__ int g_perm_ent[NG];
__device__ int g_mcnt_ent[TE];
__device__ int g_off_attr [TA + 1];
__device__ int g_perm_attr[NATT];
__device__ int g_mcnt_attr[TA];
__device__ int g_gtok_ent[NG * TE];
__device__ int g_orow_ent[NG * TE];
__device__ int g_gtok_attr[NATT * TA];
__device__ int g_orow_attr[NATT * TA];

// ---------------- helpers ------------------------------------------------------
__device__ __forceinline__ u32 smem_u32(const void* p) {
    u32 a;
    asm("{ .reg .u64 t; cvta.to.shared.u64 t, %1; cvt.u32.u64 %0, t; }"
        : "=r"(a) : "l"(p));
    return a;
}

#define LDSM_X4(r, addr) \
    asm volatile("ldmatrix.sync.aligned.m8n8.x4.shared.b16 {%0,%1,%2,%3}, [%4];" \
        : "=r"((r)[0]), "=r"((r)[1]), "=r"((r)[2]), "=r"((r)[3]) : "r"(addr))

#define LDSM_X2(r0, r1, addr) \
    asm volatile("ldmatrix.sync.aligned.m8n8.x2.shared.b16 {%0,%1}, [%2];" \
        : "=r"(r0), "=r"(r1) : "r"(addr))

#define MMA16816(c, a, b0, b1) \
    asm volatile("mma.sync.aligned.m16n8k16.row.col.f32.f16.f16.f32 " \
        "{%0,%1,%2,%3}, {%4,%5,%6,%7}, {%8,%9}, {%0,%1,%2,%3};" \
        : "+f"((c)[0]), "+f"((c)[1]), "+f"((c)[2]), "+f"((c)[3]) \
        : "r"((a)[0]), "r"((a)[1]), "r"((a)[2]), "r"((a)[3]), "r"(b0), "r"(b1))

#define CP16(dst, src, sz) \
    asm volatile("cp.async.cg.shared.global [%0], [%1], 16, %2;" \
        :: "r"(dst), "l"(src), "r"(sz) : "memory")
#define CPCOMMIT() asm volatile("cp.async.commit_group;" ::: "memory")
#define CPWAIT1()  asm volatile("cp.async.wait_group 1;"  ::: "memory")
#define CPWAIT0()  asm volatile("cp.async.wait_group 0;"  ::: "memory")

#define SWZ(o) ((o) ^ (((o) >> 3) & 0x70u))

__device__ __forceinline__ u64 cvt4h(float4 v) {
    unsigned short h[4];
    const float* pv = &v.x;
#pragma unroll
    for (int i = 0; i < 4; ++i) h[i] = __half_as_ushort(__float2half(pv[i]));
    return (u64)h[0] | ((u64)h[1] << 16) | ((u64)h[2] << 32) | ((u64)h[3] << 48);
}
__device__ __forceinline__ float4 ld4h(const __half* p) {
    __half2 a = *(const __half2*)p;
    __half2 b = *(const __half2*)(p + 2);
    float2 fa = __half22float2(a), fb = __half22float2(b);
    return make_float4(fa.x, fa.y, fb.x, fb.y);
}

// ---------------- fp32 -> fp16 conversion -------------------------------------
__global__ void cvt_rows_hi(const float* __restrict__ x,
                            __half* __restrict__ hi,
                            int rows, int K, int KP)
{
    int q = KP / 4;
    int idx = blockIdx.x * blockDim.x + threadIdx.x;
    int r = idx / q;
    if (r >= rows) return;
    int i4 = (idx - r * q) * 4;
    float4 v = make_float4(0.f, 0.f, 0.f, 0.f);
    if (i4 + 4 <= K) v = *(const float4*)(x + (long)r * K + i4);
    *(u64*)(hi + (long)r * KP + i4) = cvt4h(v);
}

__global__ void cvt_w4(const float* s0, const float* s1, const float* s2, const float* s3,
                       __half* h0, __half* h1, __half* h2, __half* h3)
{
    const float* src; __half* hi;
    switch (blockIdx.y) {
        case 0: src = s0; hi = h0; break;
        case 1: src = s1; hi = h1; break;
        case 2: src = s2; hi = h2; break;
        default: src = s3; hi = h3; break;
    }
    int q = KP3 / 4;
    int idx = blockIdx.x * blockDim.x + threadIdx.x;
    int r = idx / q;
    if (r >= G3) return;
    int i4 = (idx - r * q) * 4;
    float4 v = make_float4(0.f, 0.f, 0.f, 0.f);
    if (i4 + 4 <= WD) v = *(const float4*)(src + (long)r * WD + i4);
    *(u64*)(hi + (long)r * KP3 + i4) = cvt4h(v);
}

// ---------------- tensor GEMM (fp16 single-pass, cp.async pipeline) ----------
#define TM 128
#define TN 128
#define CK 64
#define OFF_AHI 0u
#define OFF_BHI 16384u
#define STAGE   32768u
#define TG_SMEM 65536u

__global__ void __launch_bounds__(256, 2)
tgemm(const __half* __restrict__ Ahi,
      const int* __restrict__ gather,
      const __half* __restrict__ Bhi,
      const float* __restrict__ bias,
      void* __restrict__ C, int M, int N, int K, int KP, int act, int outMap,
      const int* __restrict__ mlimit, const int* __restrict__ mlo,
      const int* __restrict__ orow, int outHalf)
{
    extern __shared__ char smem[];
    int hiM = M;
    if (mlimit) { int v = *mlimit; if (v < hiM) hiM = v; }
    int loM = mlo ? *mlo : 0;
    const int m0 = blockIdx.x * TM;
    const int n0 = blockIdx.y * TN;
    if (m0 >= hiM || m0 + TM <= loM) return;

    const u32 sbase = smem_u32(smem);
    const int tid  = threadIdx.x;
    const int wid  = tid >> 5;
    const int lane = tid & 31;
    const int wm   = wid >> 1;
    const int wn   = wid & 1;

    const int k8   = (tid & 7) * 8;
    const int rloc = tid >> 3;
    long roA[4], roB[4];
    bool vA[4], vB[4];
    u32  swR[4];
#pragma unroll
    for (int it = 0; it < 4; ++it) {
        int r = rloc + 32 * it;
        int m = m0 + r;
        vA[it] = (m >= loM && m < hiM);
        int src = vA[it] ? (gather ? gather[m] : m) : 0;
        roA[it] = (long)src * KP;
        int n = n0 + r;
        vB[it] = (n < N);
        roB[it] = (long)(vB[it] ? n : 0) * KP;
        swR[it] = SWZ((u32)(r * 128 + k8 * 2));
    }

#define FILL_CHUNK(cc, st) do { \
    int gk_ = (cc) * CK + k8; \
    u32 sb_ = sbase + (u32)(st) * STAGE; \
    bool kok_ = (gk_ < KP); \
    _Pragma("unroll") \
    for (int it = 0; it < 4; ++it) { \
        bool aok = vA[it] && kok_; u32 asz = aok ? 16u : 0u; \
        const __half* pa1 = aok ? (Ahi + roA[it] + gk_) : Ahi; \
        CP16(sb_ + OFF_AHI + swR[it], pa1, asz); \
        bool bok = vB[it] && kok_; u32 bsz = bok ? 16u : 0u; \
        const __half* pb1 = bok ? (Bhi + roB[it] + gk_) : Bhi; \
        CP16(sb_ + OFF_BHI + swR[it], pb1, bsz); \
    } \
    CPCOMMIT(); \
} while (0)

    const u32 rbA0 = (u32)((wm * 32 + (lane & 15)) * 128);
    const u32 rbA1 = rbA0 + 16u * 128u;
    const u32 rbB  = (u32)((wn * 64 + (lane & 7)) * 128);
    const u32 xorq = (u32)(lane & 7);
    const u32 qAh  = (u32)(lane >> 4);
    const u32 qBh  = (u32)((lane >> 3) & 1);

    float acc[2][8][4];
#pragma unroll
    for (int i = 0; i < 2; ++i)
#pragma unroll
        for (int j = 0; j < 8; ++j)
#pragma unroll
            for (int q = 0; q < 4; ++q) acc[i][j][q] = 0.f;

    const int nc = (K + CK - 1) / CK;

    // GUARDED=0: branch-free inner loop (interior blocks — fast path).
    // GUARDED=1: nb guard, boundary N-tile only (valid cols < 128).
#define MAIN_LOOP(GUARDED) do { \
    FILL_CHUNK(0, 0); \
    for (int c = 0; c < nc; ++c) { \
        if (c + 1 < nc) { FILL_CHUNK(c + 1, (c + 1) & 1); CPWAIT1(); } \
        else            { CPWAIT0(); } \
        __syncthreads(); \
        const u32 stb = sbase + (u32)(c & 1) * STAGE; \
        const u32 ab = stb + OFF_AHI; \
        const u32 bb = stb + OFF_BHI; \
        _Pragma("unroll") \
        for (int ks = 0; ks < 4; ++ks) { \
            u32 qa = (((u32)(2 * ks) + qAh) ^ xorq) * 16u; \
            u32 a0[4], a1[4]; \
            LDSM_X4(a0, ab + rbA0 + qa); \
            LDSM_X4(a1, ab + rbA1 + qa); \
            u32 qb = (((u32)(2 * ks) + qBh) ^ xorq) * 16u; \
            _Pragma("unroll") \
            for (int nb = 0; nb < 8; ++nb) { \
                if (GUARDED && nb >= nbMax) break; \
                u32 b0, b1; \
                LDSM_X2(b0, b1, bb + rbB + (u32)nb * 1024u + qb); \
                MMA16816(acc[0][nb], a0, b0, b1); \
                MMA16816(acc[1][nb], a1, b0, b1); \
            } \
        } \
        __syncthreads(); \
    } \
} while (0)

    if (n0 + TN <= N) {
        const int nbMax = 8;   // dead in GUARDED=0 path, keeps identifier defined
        (void)nbMax;
        MAIN_LOOP(0);
    } else {
        int nvLoc = N - n0 - wn * 64;
        int nbMax = nvLoc >= 64 ? 8 : (nvLoc <= 0 ? 0 : (nvLoc + 7) >> 3);
        MAIN_LOOP(1);
    }
#undef MAIN_LOOP
#undef FILL_CHUNK

#pragma unroll
    for (int mi = 0; mi < 2; ++mi) {
#pragma unroll
        for (int half = 0; half < 2; ++half) {
            int m = m0 + wm * 32 + mi * 16 + (lane >> 2) + half * 8;
            if (m < loM || m >= hiM) continue;
            int mm = orow ? orow[m] : m;
            long base;
            if (outMap == 0)      base = (long)mm * N;
            else if (outMap == 1) base = (long)mm * NNODE * HD;
            else                  base = ((long)(mm >> 3) * NNODE + 1 + (mm & 7)) * (long)HD;
#pragma unroll
            for (int nb = 0; nb < 8; ++nb) {
                int n = n0 + wn * 64 + nb * 8 + (lane & 3) * 2;
                if (n >= N) continue;
                float x0 = acc[mi][nb][half * 2 + 0];
                float x1 = acc[mi][nb][half * 2 + 1];
                if (bias) { x0 += bias[n]; x1 += bias[n + 1]; }
                if (act == 1)      { x0 = fmaxf(x0, 0.f); x1 = fmaxf(x1, 0.f); }
                else if (act == 2) { x0 = x0 > 0.f ? x0 : expm1f(x0);
                                     x1 = x1 > 0.f ? x1 : expm1f(x1); }
                if (outHalf) {
                    *(__half2*)((__half*)C + base + n) = __floats2half2_rn(x0, x1);
                } else {
                    *(float2*)((float*)C + base + n) = make_float2(x0, x1);
                }
            }
        }
    }
}

// ---------------- fused preprocessing (ent + attr) ---------------------------
__device__ __forceinline__ int clampL(int L, int T) {
    return L < 1 ? 1 : (L > T ? T : L);
}
__global__ void hist2(const int* __restrict__ lenE, const int* __restrict__ lenA,
                      int* __restrict__ cntE, int* __restrict__ cntA)
{
    int i = blockIdx.x * blockDim.x + threadIdx.x;
    if (i < NG)   atomicAdd(&cntE[clampL(lenE[i], TE)], 1);
    if (i < NATT) atomicAdd(&cntA[clampL(lenA[i], TA)], 1);
}
__global__ void offsets2(const int* __restrict__ cntE, int* __restrict__ offE,
                         int* __restrict__ mcntE,
                         const int* __restrict__ cntA, int* __restrict__ offA,
                         int* __restrict__ mcntA)
{
    if (threadIdx.x == 0) {
        int run = 0;
        for (int L = TE; L >= 1; --L) { offE[L] = run; run += cntE[L]; }
        for (int t = 0; t < TE; ++t) {
            int s = 0;
            for (int L = t + 1; L <= TE; ++L) s += cntE[L];
            mcntE[t] = s;
        }
    } else if (threadIdx.x == 1) {
        int run = 0;
        for (int L = TA; L >= 1; --L) { offA[L] = run; run += cntA[L]; }
        for (int t = 0; t < TA; ++t) {
            int s = 0;
            for (int L = t + 1; L <= TA; ++L) s += cntA[L];
            mcntA[t] = s;
        }
    }
}
__global__ void scatter2(const int* __restrict__ lenE, const int* __restrict__ lenA,
                         int* __restrict__ offE, int* __restrict__ permE,
                         int* __restrict__ offA, int* __restrict__ permA)
{
    int i = blockIdx.x * blockDim.x + threadIdx.x;
    if (i < NG) {
        int pos = atomicAdd(&offE[clampL(lenE[i], TE)], 1);
        permE[pos] = i;
    }
    if (i < NATT) {
        int pos = atomicAdd(&offA[clampL(lenA[i], TA)], 1);
        permA[pos] = i;
    }
}
__global__ void pairs2(const int* __restrict__ tokE, const int* __restrict__ lenE,
                       int* __restrict__ pcE, int* __restrict__ gtokE, int* __restrict__ orowE,
                       const int* __restrict__ tokA, const int* __restrict__ lenA,
                       int* __restrict__ pcA, int* __restrict__ gtokA, int* __restrict__ orowA)
{
    int p = blockIdx.x * blockDim.x + threadIdx.x;
    if (p < NG * TE) {
        int i = p / TE, t = p - i * TE;
        if (t < clampL(lenE[i], TE)) {
            int pos = atomicAdd(pcE, 1);
            gtokE[pos] = tokE[p];
            orowE[pos] = p;
        }
    }
    if (p < NATT * TA) {
        int i = p / TA, t = p - i * TA;
        if (t < clampL(lenA[i], TA)) {
            int pos = atomicAdd(pcA, 1);
            gtokA[pos] = tokA[p];
            orowA[pos] = p;
        }
    }
}

// ---------------- GRU gate update (fp16 xp/gh; t0 path uses gh = bhh) --------
__global__ void gru_gate4(const __half* __restrict__ xp,
                          const __half* __restrict__ gh,
                          const float* __restrict__ bhh_t0,
                          float* __restrict__ h,
                          __half* __restrict__ hhi,
                          const int* __restrict__ perm,
                          const int* __restrict__ mcnt,
                          int t, int T)
{
    const int Q = WD / 4;   // 75
    int idx = blockIdx.x * blockDim.x + threadIdx.x;
    int i = idx / Q;
    if (i >= *mcnt) return;
    int d = idx - i * Q;
    int orig = perm[i];
    const __half* x = xp + ((long)orig * T + t) * G3;
    float4* hp = (float4*)(h + (long)orig * WD);

    float4 xr = ld4h(x + 4 * d);
    float4 xz = ld4h(x + WD + 4 * d);
    float4 xn = ld4h(x + 2 * WD + 4 * d);
    float4 gr, gz, gn, hv;
    if (bhh_t0) {
        const float4* b = (const float4*)bhh_t0;
        gr = b[d]; gz = b[Q + d]; gn = b[2 * Q + d];
        hv = make_float4(0.f, 0.f, 0.f, 0.f);
    } else {
        const __half* g = gh + (long)i * G3;
        gr = ld4h(g + 4 * d);
        gz = ld4h(g + WD + 4 * d);
        gn = ld4h(g + 2 * WD + 4 * d);
        hv = hp[d];
    }

    float4 res;
    const float* pxr = &xr.x; const float* pxz = &xz.x; const float* pxn = &xn.x;
    const float* pgr = &gr.x; const float* pgz = &gz.x; const float* pgn = &gn.x;
    const float* phv = &hv.x; float* pres = &res.x;
#pragma unroll
    for (int c = 0; c < 4; ++c) {
        float r = 1.f / (1.f + expf(-(pxr[c] + pgr[c])));
        float z = 1.f / (1.f + expf(-(pxz[c] + pgz[c])));
        float n = tanhf(pxn[c] + r * pgn[c]);
        pres[c] = (1.f - z) * n + z * phv[c];
    }
    hp[d] = res;
    *(u64*)(hhi + (long)orig * KP3 + 4 * d) = cvt4h(res);
}

// ---------------- va/vb = Wg^T a_src / Wg^T a_dst ----------------------------
__global__ void wgt_vec_kernel(const float* __restrict__ Wg,
                               const float* __restrict__ a_src,
                               const float* __restrict__ a_dst,
                               float* __restrict__ va, float* __restrict__ vb)
{
    int k = blockIdx.x * blockDim.x + threadIdx.x;
    if (k >= HD) return;
    float sa = 0.f, sb = 0.f;
    for (int d = 0; d < HD; ++d) {
        float w = Wg[(long)d * HD + k];
        sa += w * a_src[d];
        sb += w * a_dst[d];
    }
    va[k] = sa;
    vb[k] = sb;
}

// ---------------- GAT dots + softmax + node mix (writes fp16 hi) -------------
__global__ void gat_mix_kernel(const float* __restrict__ nodes,
                               const float* __restrict__ va,
                               const float* __restrict__ vb,
                               const unsigned char* __restrict__ amask,
                               __half* __restrict__ mhi)
{
    int g = blockIdx.x;
    const float* base = nodes + (long)g * NNODE * HD;
    __shared__ float sdots[10];
    __shared__ float salpha[NNODE];

    int tid  = threadIdx.x;
    int warp = tid >> 5, lane = tid & 31;

    float partial = 0.f;
    if (warp < 9) {
        const float* row = base + warp * HD;
        for (int d = lane; d < HD; d += 32) partial += row[d] * vb[d];
    } else {
        for (int d = lane; d < HD; d += 32) partial += base[d] * va[d];
    }
#pragma unroll
    for (int off = 16; off; off >>= 1)
        partial += __shfl_down_sync(0xffffffffu, partial, off);
    if (lane == 0) sdots[warp] = partial;
    __syncthreads();

    if (tid == 0) {
        float es0 = sdots[9];
        float e[NNODE];
#pragma unroll
        for (int j = 0; j < NNODE; ++j) {
            bool valid;
            if (j == 0) valid = true;
            else {
                const unsigned char* mk = amask + ((long)g * NA + (j - 1)) * TA;
                valid = !(mk[0] && mk[1] && mk[2] && mk[3]);
            }
            if (valid) {
                float v = es0 + sdots[j];
                e[j] = v > 0.f ? v : 0.2f * v;
            } else e[j] = -1e9f;
        }
        float mx = e[0];
#pragma unroll
        for (int j = 1; j < NNODE; ++j) mx = fmaxf(mx, e[j]);
        float s = 0.f, ex[NNODE];
#pragma unroll
        for (int j = 0; j < NNODE; ++j) { ex[j] = expf(e[j] - mx); s += ex[j]; }
        float inv = 1.f / s;
#pragma unroll
        for (int j = 0; j < NNODE; ++j) salpha[j] = ex[j] * inv;
    }
    __syncthreads();

    for (int d4 = tid; d4 < HD / 4; d4 += blockDim.x) {
        float4 s4;
        float* ps = &s4.x;
#pragma unroll
        for (int q = 0; q < 4; ++q) {
            int d = d4 * 4 + q;
            float s = 0.f;
#pragma unroll
            for (int j = 0; j < NNODE; ++j) s += salpha[j] * base[j * HD + d];
            ps[q] = s;
        }
        *(u64*)(mhi + (long)g * HD + 4 * d4) = cvt4h(s4);
    }
}

// ---------------- launch ------------------------------------------------------
extern "C" void kernel_launch(void* const* d_in, const int* in_sizes, int n_in,
                              void* d_out, int out_size)
{
    const int*   ent_tok  = (const int*)  d_in[0];
    const int*   ent_len  = (const int*)  d_in[1];
    const int*   at_tok   = (const int*)  d_in[3];
    const int*   at_len   = (const int*)  d_in[4];
    const unsigned char* at_mask = (const unsigned char*)d_in[5];
    const float* emb      = (const float*)d_in[6];
    const float* Wih_ent  = (const float*)d_in[7];
    const float* Whh_ent  = (const float*)d_in[8];
    const float* bih_ent  = (const float*)d_in[9];
    const float* bhh_ent  = (const float*)d_in[10];
    const float* Wih_attr = (const float*)d_in[11];
    const float* Whh_attr = (const float*)d_in[12];
    const float* bih_attr = (const float*)d_in[13];
    const float* bhh_attr = (const float*)d_in[14];
    const float* Wfc      = (const float*)d_in[15];
    const float* bfc      = (const float*)d_in[16];
    const float* Wg       = (const float*)d_in[17];
    const float* a_src    = (const float*)d_in[18];
    const float* a_dst    = (const float*)d_in[19];
    float* out = (float*)d_out;

    static cudaStream_t s2 = nullptr, s3 = nullptr;
    static cudaEvent_t evF = nullptr, evJ = nullptr, evFC = nullptr;
    static cudaEvent_t evG[TA] = {};
    if (!s2) {
        cudaStreamCreateWithFlags(&s2, cudaStreamNonBlocking);
        cudaStreamCreateWithFlags(&s3, cudaStreamNonBlocking);
        cudaEventCreateWithFlags(&evF, cudaEventDisableTiming);
        cudaEventCreateWithFlags(&evJ, cudaEventDisableTiming);
        cudaEventCreateWithFlags(&evFC, cudaEventDisableTiming);
        for (int t = 0; t < TA; ++t)
            cudaEventCreateWithFlags(&evG[t], cudaEventDisableTiming);
    }

    __half *xp_ent, *xp_attr, *ghE, *ghA;
    float *h_ent, *h_attr, *nodes, *va, *vb;
    int *ctr, *offE, *permE, *mcntE, *offA, *permA, *mcntA;
    int *gtokE, *orowE, *gtokA, *orowA;
    __half *embH, *wiheH, *whheH, *wihaH, *whhaH, *wfcH, *wgH;
    __half *heH, *haH, *mixH;

    cudaGetSymbolAddress((void**)&xp_ent,  g_xp_ent);
    cudaGetSymbolAddress((void**)&xp_attr, g_xp_attr);
    cudaGetSymbolAddress((void**)&ghE,     g_gh_ent);
    cudaGetSymbolAddress((void**)&ghA,     g_gh_attr);
    cudaGetSymbolAddress((void**)&h_ent,   g_h_ent);
    cudaGetSymbolAddress((void**)&h_attr,  g_h_attr);
    cudaGetSymbolAddress((void**)&nodes,   g_nodes);
    cudaGetSymbolAddress((void**)&va,      g_va);
    cudaGetSymbolAddress((void**)&vb,      g_vb);
    cudaGetSymbolAddress((void**)&ctr,   g_ctr);
    cudaGetSymbolAddress((void**)&offE,  g_off_ent);
    cudaGetSymbolAddress((void**)&permE, g_perm_ent);
    cudaGetSymbolAddress((void**)&mcntE, g_mcnt_ent);
    cudaGetSymbolAddress((void**)&offA,  g_off_attr);
    cudaGetSymbolAddress((void**)&permA, g_perm_attr);
    cudaGetSymbolAddress((void**)&mcntA, g_mcnt_attr);
    cudaGetSymbolAddress((void**)&gtokE, g_gtok_ent);
    cudaGetSymbolAddress((void**)&orowE, g_orow_ent);
    cudaGetSymbolAddress((void**)&gtokA, g_gtok_attr);
    cudaGetSymbolAddress((void**)&orowA, g_orow_attr);
    cudaGetSymbolAddress((void**)&embH,  g_emb_hi);
    cudaGetSymbolAddress((void**)&wiheH, g_wihe_hi);
    cudaGetSymbolAddress((void**)&whheH, g_whhe_hi);
    cudaGetSymbolAddress((void**)&wihaH, g_wiha_hi);
    cudaGetSymbolAddress((void**)&whhaH, g_whha_hi);
    cudaGetSymbolAddress((void**)&wfcH,  g_wfc_hi);
    cudaGetSymbolAddress((void**)&wgH,   g_wg_hi);
    cudaGetSymbolAddress((void**)&heH,   g_he_hi);
    cudaGetSymbolAddress((void**)&haH,   g_ha_hi);
    cudaGetSymbolAddress((void**)&mixH,  g_mix_hi);

    int* cntE = ctr + 0;
    int* cntA = ctr + 10;
    int* pcE  = ctr + 20;
    int* pcA  = ctr + 21;

    cudaFuncSetAttribute(tgemm, cudaFuncAttributeMaxDynamicSharedMemorySize, TG_SMEM);

    cudaMemsetAsync(ctr, 0, 32 * sizeof(int));

    // Wg conversion + attention vectors on s2 (independent of main prefix)
    cvt_rows_hi<<<(HD * (HD / 4) + 255) / 256, 256, 0, s2>>>(Wg, wgH, HD, HD, HD);
    wgt_vec_kernel<<<(HD + 255) / 256, 256, 0, s2>>>(Wg, a_src, a_dst, va, vb);

    // main-prefix conversions + preprocessing
    const int q3 = KP3 / 4;
    cvt_rows_hi<<<(V * q3 + 255) / 256, 256>>>(emb, embH, V, WD, KP3);
    cvt_w4<<<dim3((G3 * q3 + 255) / 256, 4), 256>>>(
        Wih_ent, Whh_ent, Wih_attr, Whh_attr, wiheH, whheH, wihaH, whhaH);
    cvt_rows_hi<<<(HD * q3 + 255) / 256, 256>>>(Wfc, wfcH, HD, WD, KP3);

    hist2<<<(NATT + 255) / 256, 256>>>(ent_len, at_len, cntE, cntA);
    offsets2<<<1, 32>>>(cntE, offE, mcntE, cntA, offA, mcntA);
    scatter2<<<(NATT + 255) / 256, 256>>>(ent_len, at_len, offE, permE, offA, permA);
    pairs2<<<(NATT * TA + 255) / 256, 256>>>(ent_tok, ent_len, pcE, gtokE, orowE,
                                             at_tok, at_len, pcA, gtokA, orowA);

    // fork entity chain (incl. its xp GEMM) right after preprocessing
    cudaEventRecord(evF, 0);
    cudaStreamWaitEvent(s2, evF, 0);

    const int nt900  = (G3 + TN - 1) / TN;   // 8
    const int nt1024 = HD / TN;              // 8

    // ---- entity chain (stream s2): xp_ent + GRU + FC ----
    tgemm<<<dim3(NG * TE / TM, nt900), 256, TG_SMEM, s2>>>(
        embH, gtokE, wiheH, bih_ent, xp_ent,
        NG * TE, G3, WD, KP3, 0, 0, pcE, nullptr, orowE, 1);
    gru_gate4<<<(NG * 75 + 255) / 256, 256, 0, s2>>>(
        xp_ent, nullptr, bhh_ent, h_ent, heH, permE, mcntE + 0, 0, TE);
    for (int t = 1; t < TE; ++t) {
        tgemm<<<dim3(NG / TM, nt900), 256, TG_SMEM, s2>>>(
            heH, permE, whheH, bhh_ent, ghE,
            NG, G3, WD, KP3, 0, 0, mcntE + t, nullptr, nullptr, 1);
        gru_gate4<<<(NG * 75 + 255) / 256, 256, 0, s2>>>(
            xp_ent, ghE, nullptr, h_ent, heH, permE, mcntE + t, t, TE);
    }
    tgemm<<<dim3(NG / TM, nt1024), 256, TG_SMEM, s2>>>(
        heH, nullptr, wfcH, bfc, nodes,
        NG, HD, WD, KP3, 1, 1, nullptr, nullptr, nullptr, 0);
    cudaEventRecord(evJ, s2);

    // ---- attribute chain (main stream) with retired-row FC slices on s3 ----
    tgemm<<<dim3(NATT * TA / TM, nt900), 256, TG_SMEM>>>(
        embH, gtokA, wihaH, bih_attr, xp_attr,
        NATT * TA, G3, WD, KP3, 0, 0, pcA, nullptr, orowA, 1);
    gru_gate4<<<(NATT * 75 + 255) / 256, 256>>>(
        xp_attr, nullptr, bhh_attr, h_attr, haH, permA, mcntA + 0, 0, TA);
    cudaEventRecord(evG[0], 0);
    for (int t = 1; t < TA; ++t) {
        tgemm<<<dim3(NATT / TM, nt900), 256, TG_SMEM>>>(
            haH, permA, whhaH, bhh_attr, ghA,
            NATT, G3, WD, KP3, 0, 0, mcntA + t, nullptr, nullptr, 1);
        gru_gate4<<<(NATT * 75 + 255) / 256, 256>>>(
            xp_attr, ghA, nullptr, h_attr, haH, permA, mcntA + t, t, TA);
        cudaEventRecord(evG[t], 0);
    }
    // FC slices: after gate t, rows [mcnt[t+1], mcnt[t]) are final
    for (int t = 0; t < TA; ++t) {
        cudaStreamWaitEvent(s3, evG[t], 0);
        const int* hiP = mcntA + t;
        const int* loP = (t + 1 < TA) ? (mcntA + t + 1) : nullptr;
        tgemm<<<dim3(NATT / TM, nt1024), 256, TG_SMEM, s3>>>(
            haH, permA, wfcH, bfc, nodes,
            NATT, HD, WD, KP3, 1, 2, hiP, loP, permA, 0);
    }
    cudaEventRecord(evFC, s3);

    // join entity + FC streams
    cudaStreamWaitEvent(0, evJ, 0);
    cudaStreamWaitEvent(0, evFC, 0);

    // GAT: dots + alpha + mix (fp16 out)
    gat_mix_kernel<<<NG, 320>>>(nodes, va, vb, at_mask, mixH);

    // out = elu(mix @ Wg^T)
    tgemm<<<dim3(NG / TM, nt1024), 256, TG_SMEM>>>(
        mixH, nullptr, wgH, nullptr, out,
        NG, HD, HD, HD, 2, 0, nullptr, nullptr, nullptr, 0);
}